// round 13
// baseline (speedup 1.0000x reference)
#include <cuda_runtime.h>
#include <cuda_fp16.h>
#include <cstdint>

// GCN: out2 = GCNagg(relu(GCNagg(x@W1) + b1) @ W2) + b2
// R13: R11 topology (measured best) + BK 32->64 in the fp16 GEMMs
//      (4 syncs/block instead of 8, 2x longer MMA runs; LDT=72 keeps
//      ldmatrix conflict-free; 72KB smem with opt-in attribute).

#define N_NODES 50000
#define F_IN    256
#define F_HID   256
#define F_OUT   128
#define MAX_E   320000

// -------- scratch (device globals; no allocations allowed) --------
__device__ __align__(16) __half g_h1f [(size_t)N_NODES * F_HID];
__device__ __align__(16) __half g_agg1[(size_t)N_NODES * F_HID];
__device__ __align__(16) __half g_h2f [(size_t)N_NODES * F_OUT];
__device__ __align__(16) __half g_w1t [(size_t)F_IN  * F_HID];
__device__ __align__(16) __half g_w2t [(size_t)F_HID * F_OUT];
__device__ float g_dinv  [N_NODES];
__device__ int   g_indeg [N_NODES];
__device__ int   g_off   [N_NODES + 1];
__device__ int   g_cursor[N_NODES];
__device__ int   g_bsum  [256];
__device__ int   g_bpre  [256];
__device__ int   g_scan_count;
__device__ int   g_scan_ready;
__device__ int   g_elist [MAX_E];
__device__ int   g_is64;

// ======================= fp16 warp-MMA GEMM (double-buffered, BK=64) ========
__device__ __forceinline__ void mma_16x8x16(float* c, const uint32_t* a, const uint32_t* b) {
    asm volatile(
        "mma.sync.aligned.m16n8k16.row.col.f32.f16.f16.f32 "
        "{%0,%1,%2,%3}, {%4,%5,%6,%7}, {%8,%9}, {%0,%1,%2,%3};"
        : "+f"(c[0]), "+f"(c[1]), "+f"(c[2]), "+f"(c[3])
        : "r"(a[0]), "r"(a[1]), "r"(a[2]), "r"(a[3]), "r"(b[0]), "r"(b[1]));
}

#define LDSM_X4(r0, r1, r2, r3, addr) \
    asm volatile("ldmatrix.sync.aligned.m8n8.x4.shared.b16 {%0,%1,%2,%3}, [%4];" \
                 : "=r"(r0), "=r"(r1), "=r"(r2), "=r"(r3) : "r"(addr))

static constexpr int BM = 128, BN = 128, BK = 64;
static constexpr int LDT = 72;                   // smem row stride in halves (144B)
static constexpr int ASZ = BM * LDT;             // halves
static constexpr int BSZ = BN * LDT;             // halves
static constexpr int STAGE = ASZ + BSZ;          // halves per buffer
static constexpr int GEMM_SMEM = 2 * STAGE * 2;  // 73728 bytes

template <bool A_HALF, bool SCALE_EPI>
__global__ __launch_bounds__(256)
void mma_gemm_fp16(const void* __restrict__ Aptr,
                   const __half* __restrict__ BT,   // [N][K] fp16
                   __half* __restrict__ C16,
                   int M, int N, int K) {
    extern __shared__ __half smemh[];

    const int tid  = threadIdx.x;
    const int wid  = tid >> 5;
    const int lane = tid & 31;
    const int g    = lane >> 2;
    const int t    = lane & 3;
    const int wrow = (wid >> 2) * 64;
    const int wcol = (wid & 3) * 32;
    const int rowBase = blockIdx.y * BM;
    const int colBase = blockIdx.x * BN;

    const int a_r = lane & 15;
    const int a_c = (lane >> 4) * 8;
    const int b_n = ((lane >> 4) << 3) + (lane & 7);
    const int b_k = ((lane >> 3) & 1) * 8;

    float4 a_stf[8];   // A fp32 staging: 128x64 floats / 256 thr = 8 float4
    uint4  a_sth[4];   // A fp16 staging: 128x64 halves / 256 thr = 4 uint4
    uint4  b_st[4];    // B fp16 staging: 128x64 halves / 256 thr = 4 uint4

    auto load_stage = [&](int k0) {
        if (A_HALF) {
            const __half* Ah = (const __half*)Aptr;
            #pragma unroll
            for (int it = 0; it < 4; it++) {
                const int idx = tid + it * 256;
                const int r  = idx >> 3;          // 8 uint4 per 64-half row
                const int c8 = (idx & 7) * 8;
                const int gr = rowBase + r;
                a_sth[it] = (gr < M)
                    ? *reinterpret_cast<const uint4*>(Ah + (size_t)gr * K + k0 + c8)
                    : make_uint4(0u, 0u, 0u, 0u);
            }
        } else {
            const float* Af = (const float*)Aptr;
            #pragma unroll
            for (int it = 0; it < 8; it++) {
                const int idx = tid + it * 256;
                const int r  = idx >> 4;          // 16 float4 per 64-float row
                const int c4 = (idx & 15) * 4;
                const int gr = rowBase + r;
                a_stf[it] = (gr < M)
                    ? *reinterpret_cast<const float4*>(Af + (size_t)gr * K + k0 + c4)
                    : make_float4(0.f, 0.f, 0.f, 0.f);
            }
        }
        #pragma unroll
        for (int it = 0; it < 4; it++) {
            const int idx = tid + it * 256;
            const int n  = idx >> 3;
            const int c8 = (idx & 7) * 8;
            b_st[it] = *reinterpret_cast<const uint4*>(
                BT + (size_t)(colBase + n) * K + k0 + c8);
        }
    };

    auto store_stage = [&](__half* As, __half* Bs) {
        if (A_HALF) {
            #pragma unroll
            for (int it = 0; it < 4; it++) {
                const int idx = tid + it * 256;
                const int r  = idx >> 3;
                const int c8 = (idx & 7) * 8;
                *reinterpret_cast<uint4*>(As + r * LDT + c8) = a_sth[it];
            }
        } else {
            #pragma unroll
            for (int it = 0; it < 8; it++) {
                const int idx = tid + it * 256;
                const int r  = idx >> 4;
                const int c4 = (idx & 15) * 4;
                const __half2 h01 = __floats2half2_rn(a_stf[it].x, a_stf[it].y);
                const __half2 h23 = __floats2half2_rn(a_stf[it].z, a_stf[it].w);
                uint2 u;
                u.x = *reinterpret_cast<const uint32_t*>(&h01);
                u.y = *reinterpret_cast<const uint32_t*>(&h23);
                *reinterpret_cast<uint2*>(As + r * LDT + c4) = u;
            }
        }
        #pragma unroll
        for (int it = 0; it < 4; it++) {
            const int idx = tid + it * 256;
            const int n  = idx >> 3;
            const int c8 = (idx & 7) * 8;
            *reinterpret_cast<uint4*>(Bs + n * LDT + c8) = b_st[it];
        }
    };

    float acc[4][4][4];
    #pragma unroll
    for (int i = 0; i < 4; i++)
        #pragma unroll
        for (int j = 0; j < 4; j++)
            #pragma unroll
            for (int c = 0; c < 4; c++) acc[i][j][c] = 0.0f;

    load_stage(0);

    const int ntiles = K / BK;
    for (int it = 0; it < ntiles; it++) {
        __half* As = smemh + (it & 1) * STAGE;
        __half* Bs = As + ASZ;

        store_stage(As, Bs);
        __syncthreads();
        if (it + 1 < ntiles) load_stage((it + 1) * BK);

        #pragma unroll
        for (int ks = 0; ks < BK / 16; ks++) {
            const int kk = ks * 16;
            uint32_t af[4][4], bf[4][2];
            #pragma unroll
            for (int i = 0; i < 4; i++) {
                const uint32_t addr = (uint32_t)__cvta_generic_to_shared(
                    &As[(wrow + i * 16 + a_r) * LDT + kk + a_c]);
                LDSM_X4(af[i][0], af[i][1], af[i][2], af[i][3], addr);
            }
            #pragma unroll
            for (int p = 0; p < 2; p++) {
                const uint32_t addr = (uint32_t)__cvta_generic_to_shared(
                    &Bs[(wcol + p * 16 + b_n) * LDT + kk + b_k]);
                LDSM_X4(bf[2 * p][0], bf[2 * p][1], bf[2 * p + 1][0], bf[2 * p + 1][1], addr);
            }
            #pragma unroll
            for (int i = 0; i < 4; i++)
                #pragma unroll
                for (int j = 0; j < 4; j++)
                    mma_16x8x16(acc[i][j], af[i], bf[j]);
        }
    }

    #pragma unroll
    for (int i = 0; i < 4; i++) {
        #pragma unroll
        for (int half = 0; half < 2; half++) {
            const int gr = rowBase + wrow + i * 16 + g + half * 8;
            if (gr < M) {
                const float d = SCALE_EPI ? g_dinv[gr] : 1.0f;
                __half* dst = C16 + (size_t)gr * N + colBase + wcol;
                #pragma unroll
                for (int j = 0; j < 4; j++) {
                    const __half2 hv = __floats2half2_rn(acc[i][j][half * 2] * d,
                                                         acc[i][j][half * 2 + 1] * d);
                    *reinterpret_cast<__half2*>(dst + j * 8 + 2 * t) = hv;
                }
            }
        }
    }
}

// -------- weight transpose+convert: W[K][N] fp32 -> WT[N][K] fp16 -----------
__global__ void transpose_w_kernel(const float* __restrict__ W,
                                   __half* __restrict__ WT,
                                   int K, int N) {
    __shared__ float tile[32][33];
    const int k0 = blockIdx.y * 32;
    const int n0 = blockIdx.x * 32;
    const int tx = threadIdx.x, ty = threadIdx.y;   // 32 x 8
    #pragma unroll
    for (int i = 0; i < 32; i += 8)
        tile[ty + i][tx] = W[(size_t)(k0 + ty + i) * N + n0 + tx];
    __syncthreads();
    #pragma unroll
    for (int i = 0; i < 32; i += 8)
        WT[(size_t)(n0 + ty + i) * K + k0 + tx] = __float2half_rn(tile[tx][ty + i]);
}

// ======================= graph-side kernels =================================
__device__ __forceinline__ long long edge_get(const void* p, long long i) {
    return g_is64 ? ((const long long*)p)[i] : (long long)((const int*)p)[i];
}

__global__ void prep_kernel(const unsigned int* __restrict__ w, int nwords, int n) {
    if ((int)blockIdx.x == (int)gridDim.x - 1) {
        __shared__ unsigned int s_or;
        if (threadIdx.x == 0) {
            s_or = 0u;
            g_scan_count = 0;
            g_scan_ready = 0;
        }
        __syncthreads();
        unsigned int v = 0u;
        for (int i = 2 * threadIdx.x + 1; i < nwords; i += 2 * blockDim.x) v |= w[i];
        atomicOr(&s_or, v);
        __syncthreads();
        if (threadIdx.x == 0) g_is64 = (s_or == 0u) ? 1 : 0;
        return;
    }
    const int i = blockIdx.x * blockDim.x + threadIdx.x;
    if (i < n) g_indeg[i] = 0;
}

__global__ void indeg_kernel(const void* __restrict__ edges, int E) {
    int e = blockIdx.x * blockDim.x + threadIdx.x;
    if (e < E) atomicAdd(&g_indeg[(int)edge_get(edges, e)], 1);
}

__global__ void scan_fused_kernel(int n, int nb) {
    __shared__ int s[256];
    __shared__ int s_prev;
    __shared__ int s_islast;
    const int t = threadIdx.x;
    const int bid = blockIdx.x;
    const int i = bid * 256 + t;

    int v = 0;
    if (i < n) {
        v = g_indeg[i];
        g_dinv[i] = rsqrtf((float)(v + 1));
    }
    s[t] = v;
    __syncthreads();
    #pragma unroll
    for (int off = 1; off < 256; off <<= 1) {
        int x = (t >= off) ? s[t - off] : 0;
        __syncthreads();
        s[t] += x;
        __syncthreads();
    }
    const int incl  = s[t];
    const int total = s[255];

    if (t == 0) {
        g_bsum[bid] = total;
        __threadfence();
        const int done = atomicAdd(&g_scan_count, 1);
        s_islast = (done == nb - 1) ? 1 : 0;
    }
    __syncthreads();

    if (s_islast) {
        int bv = (t < nb) ? g_bsum[t] : 0;
        s[t] = bv;
        __syncthreads();
        #pragma unroll
        for (int off = 1; off < 256; off <<= 1) {
            int x = (t >= off) ? s[t - off] : 0;
            __syncthreads();
            s[t] += x;
            __syncthreads();
        }
        if (t < nb) g_bpre[t] = s[t] - bv;
        __threadfence();
        __syncthreads();
        if (t == 0) atomicExch(&g_scan_ready, 1);
    }

    if (t == 0) {
        while (atomicAdd(&g_scan_ready, 0) == 0) {}
        __threadfence();
        s_prev = g_bpre[bid];
    }
    __syncthreads();

    if (i < n) {
        const int fin = incl + s_prev;
        g_off[i + 1] = fin;
        if (i + 1 < n) g_cursor[i + 1] = fin;
        if (i == 0) { g_off[0] = 0; g_cursor[0] = 0; }
    }
}

__global__ void fill_kernel(const void* __restrict__ edges, int E) {
    int e = blockIdx.x * blockDim.x + threadIdx.x;
    if (e >= E) return;
    const int r = (int)edge_get(edges, e);
    const int c = (int)edge_get(edges, (long long)E + e);
    const int slot = atomicAdd(&g_cursor[r], 1);
    g_elist[slot] = c;
}

// ---- gather aggregation: SPLIT warps per destination node (R11 version) ----
template <int F, int SPLIT, bool RELU, bool SCALE_NBR, bool OUT_HALF>
__global__ void gather_kernel(const __half* __restrict__ hf,
                              const float* __restrict__ bias,
                              void* __restrict__ outp,
                              int M) {
    const int wunit = (int)((blockIdx.x * blockDim.x + threadIdx.x) >> 5);
    const int lane = threadIdx.x & 31;
    const int node = wunit / SPLIT;
    const int part = wunit - node * SPLIT;
    if (node >= M) return;
    const int fofs = part * (F / SPLIT) + lane * 4;

    const float d = g_dinv[node];
    const float selfs = SCALE_NBR ? d : 1.0f;

    float acc[4];
    {
        const uint2 raw = __ldg(reinterpret_cast<const uint2*>(hf + (size_t)node * F + fofs));
        const __half2* hp = reinterpret_cast<const __half2*>(&raw);
        const float2 f0 = __half22float2(hp[0]);
        const float2 f1 = __half22float2(hp[1]);
        acc[0] = selfs * f0.x; acc[1] = selfs * f0.y;
        acc[2] = selfs * f1.x; acc[3] = selfs * f1.y;
    }

    const int beg = g_off[node];
    const int end = g_off[node + 1];
    for (int i = beg; i < end; i += 32) {
        const int   my  = (i + lane < end) ? g_elist[i + lane] : 0;
        const float myd = SCALE_NBR ? g_dinv[my] : 1.0f;
        const int cnt = min(32, end - i);
        #pragma unroll 4
        for (int j = 0; j < cnt; j++) {
            const int   c  = __shfl_sync(0xffffffffu, my,  j);
            const float dc = SCALE_NBR ? __shfl_sync(0xffffffffu, myd, j) : 1.0f;
            const uint2 raw = __ldg(reinterpret_cast<const uint2*>(hf + (size_t)c * F + fofs));
            const __half2* hp = reinterpret_cast<const __half2*>(&raw);
            const float2 f0 = __half22float2(hp[0]);
            const float2 f1 = __half22float2(hp[1]);
            if (SCALE_NBR) {
                acc[0] = fmaf(dc, f0.x, acc[0]); acc[1] = fmaf(dc, f0.y, acc[1]);
                acc[2] = fmaf(dc, f1.x, acc[2]); acc[3] = fmaf(dc, f1.y, acc[3]);
            } else {
                acc[0] += f0.x; acc[1] += f0.y;
                acc[2] += f1.x; acc[3] += f1.y;
            }
        }
    }

    const float4 bv = __ldg(reinterpret_cast<const float4*>(bias + fofs));
    float4 v;
    v.x = fmaf(d, acc[0], bv.x);
    v.y = fmaf(d, acc[1], bv.y);
    v.z = fmaf(d, acc[2], bv.z);
    v.w = fmaf(d, acc[3], bv.w);
    if (RELU) {
        v.x = fmaxf(v.x, 0.f); v.y = fmaxf(v.y, 0.f);
        v.z = fmaxf(v.z, 0.f); v.w = fmaxf(v.w, 0.f);
    }
    if (OUT_HALF) {
        const __half2 h01 = __floats2half2_rn(v.x, v.y);
        const __half2 h23 = __floats2half2_rn(v.z, v.w);
        uint2 u;
        u.x = *reinterpret_cast<const uint32_t*>(&h01);
        u.y = *reinterpret_cast<const uint32_t*>(&h23);
        *reinterpret_cast<uint2*>((__half*)outp + (size_t)node * F + fofs) = u;
    } else {
        *reinterpret_cast<float4*>((float*)outp + (size_t)node * F + fofs) = v;
    }
}

// -------- static side stream for CSR/GEMM1 overlap (created pre-capture) ----
static cudaStream_t g_s2 = nullptr;
static cudaEvent_t  g_evFork = nullptr, g_evJoin = nullptr;
static bool g_streams_ok = false;
namespace {
struct StreamInit {
    StreamInit() {
        g_streams_ok =
            cudaStreamCreateWithFlags(&g_s2, cudaStreamNonBlocking) == cudaSuccess &&
            cudaEventCreateWithFlags(&g_evFork, cudaEventDisableTiming) == cudaSuccess &&
            cudaEventCreateWithFlags(&g_evJoin, cudaEventDisableTiming) == cudaSuccess;
    }
} g_stream_init;
}

// ---------------------------------------------------------------
extern "C" void kernel_launch(void* const* d_in, const int* in_sizes, int n_in,
                              void* d_out, int out_size) {
    const float* x     = (const float*)d_in[0];
    const void*  edges = d_in[1];
    const float* W1    = (const float*)d_in[2];
    const float* b1    = (const float*)d_in[3];
    const float* W2    = (const float*)d_in[4];
    const float* b2    = (const float*)d_in[5];
    float* out = (float*)d_out;

    const int M = in_sizes[0] / F_IN;
    const int E = in_sizes[1] / 2;
    const int NB = (M + 255) / 256;

    __half* h1f  = nullptr;  cudaGetSymbolAddress((void**)&h1f,  g_h1f);
    __half* agg1 = nullptr;  cudaGetSymbolAddress((void**)&agg1, g_agg1);
    __half* h2f  = nullptr;  cudaGetSymbolAddress((void**)&h2f,  g_h2f);
    __half* w1t  = nullptr;  cudaGetSymbolAddress((void**)&w1t,  g_w1t);
    __half* w2t  = nullptr;  cudaGetSymbolAddress((void**)&w2t,  g_w2t);

    // 72KB dynamic smem needs the opt-in attribute
    cudaFuncSetAttribute(mma_gemm_fp16<false, false>,
                         cudaFuncAttributeMaxDynamicSharedMemorySize, GEMM_SMEM);
    cudaFuncSetAttribute(mma_gemm_fp16<true, true>,
                         cudaFuncAttributeMaxDynamicSharedMemorySize, GEMM_SMEM);

    const dim3 grid1(F_HID / BN, (M + BM - 1) / BM);
    const dim3 grid2(F_OUT / BN, (M + BM - 1) / BM);
    const dim3 tblk(32, 8);
    const int eb = (E + 255) / 256;
    int nwords = 2 * E;
    if (nwords > 4096) nwords = 4096;

    if (g_streams_ok) {
        // side: prep (detect+zero+flags) -> indeg -> fused scan -> fill -> w2t
        cudaEventRecord(g_evFork, 0);
        cudaStreamWaitEvent(g_s2, g_evFork, 0);

        prep_kernel<<<NB + 1, 256, 0, g_s2>>>((const unsigned int*)edges, nwords, M);
        indeg_kernel<<<eb, 256, 0, g_s2>>>(edges, E);
        scan_fused_kernel<<<NB, 256, 0, g_s2>>>(M, NB);
        fill_kernel<<<eb, 256, 0, g_s2>>>(edges, E);
        transpose_w_kernel<<<dim3(F_OUT / 32, F_HID / 32), tblk, 0, g_s2>>>(W2, w2t, F_HID, F_OUT);
        cudaEventRecord(g_evJoin, g_s2);

        // main: w1t transpose -> GEMM1 (no dependency on detect/CSR)
        transpose_w_kernel<<<dim3(F_HID / 32, F_IN / 32), tblk>>>(W1, w1t, F_IN, F_HID);
        mma_gemm_fp16<false, false><<<grid1, 256, GEMM_SMEM>>>(x, w1t, h1f, M, F_HID, F_IN);

        cudaStreamWaitEvent(0, g_evJoin, 0);
    } else {
        prep_kernel<<<NB + 1, 256>>>((const unsigned int*)edges, nwords, M);
        indeg_kernel<<<eb, 256>>>(edges, E);
        scan_fused_kernel<<<NB, 256>>>(M, NB);
        fill_kernel<<<eb, 256>>>(edges, E);
        transpose_w_kernel<<<dim3(F_HID / 32, F_IN / 32), tblk>>>(W1, w1t, F_IN, F_HID);
        transpose_w_kernel<<<dim3(F_OUT / 32, F_HID / 32), tblk>>>(W2, w2t, F_HID, F_OUT);
        mma_gemm_fp16<false, false><<<grid1, 256, GEMM_SMEM>>>(x, w1t, h1f, M, F_HID, F_IN);
    }

    // gather1 (2 warps/node): agg1[r] = relu(dinv[r]*(dinv[r]*h1[r] + sum dinv[c]*h1[c]) + b1)
    {
        const long long warps = (long long)M * 2;
        gather_kernel<F_HID, 2, true, true, true>
            <<<(int)((warps * 32 + 255) / 256), 256>>>(h1f, b1, agg1, M);
    }

    // GEMM2: hs2 = (agg1 @ W2) * dinv[row]  (A fp16 direct)
    mma_gemm_fp16<true, true><<<grid2, 256, GEMM_SMEM>>>(agg1, w2t, h2f, M, F_OUT, F_HID);

    // gather2 (1 warp/node): out[r] = dinv[r]*(hs2[r] + sum hs2[c]) + b2
    {
        const long long warps = (long long)M;
        gather_kernel<F_OUT, 1, false, false, false>
            <<<(int)((warps * 32 + 255) / 256), 256>>>(h2f, b2, out, M);
    }
}

// round 14
// speedup vs baseline: 1.0682x; 1.0682x over previous
#include <cuda_runtime.h>
#include <cuda_fp16.h>
#include <cstdint>

// GCN: out2 = GCNagg(relu(GCNagg(x@W1) + b1) @ W2) + b2
// R14: R11 (measured best) with indeg/fill processing 4 edges per thread
//      (MLP=4, 4x fewer blocks) to unbind the side-chain join.

#define N_NODES 50000
#define F_IN    256
#define F_HID   256
#define F_OUT   128
#define MAX_E   320000

// -------- scratch (device globals; no allocations allowed) --------
__device__ __align__(16) __half g_h1f [(size_t)N_NODES * F_HID];
__device__ __align__(16) __half g_agg1[(size_t)N_NODES * F_HID];
__device__ __align__(16) __half g_h2f [(size_t)N_NODES * F_OUT];
__device__ __align__(16) __half g_w1t [(size_t)F_IN  * F_HID];
__device__ __align__(16) __half g_w2t [(size_t)F_HID * F_OUT];
__device__ float g_dinv  [N_NODES];
__device__ int   g_indeg [N_NODES];
__device__ int   g_off   [N_NODES + 1];
__device__ int   g_cursor[N_NODES];
__device__ int   g_bsum  [256];
__device__ int   g_bpre  [256];
__device__ int   g_scan_count;
__device__ int   g_scan_ready;
__device__ int   g_elist [MAX_E];
__device__ int   g_is64;

// ======================= fp16 warp-MMA GEMM (double-buffered, BK=32) ========
__device__ __forceinline__ void mma_16x8x16(float* c, const uint32_t* a, const uint32_t* b) {
    asm volatile(
        "mma.sync.aligned.m16n8k16.row.col.f32.f16.f16.f32 "
        "{%0,%1,%2,%3}, {%4,%5,%6,%7}, {%8,%9}, {%0,%1,%2,%3};"
        : "+f"(c[0]), "+f"(c[1]), "+f"(c[2]), "+f"(c[3])
        : "r"(a[0]), "r"(a[1]), "r"(a[2]), "r"(a[3]), "r"(b[0]), "r"(b[1]));
}

#define LDSM_X4(r0, r1, r2, r3, addr) \
    asm volatile("ldmatrix.sync.aligned.m8n8.x4.shared.b16 {%0,%1,%2,%3}, [%4];" \
                 : "=r"(r0), "=r"(r1), "=r"(r2), "=r"(r3) : "r"(addr))

static constexpr int BM = 128, BN = 128, BK = 32;
static constexpr int LDT = 40;                   // smem row stride in halves (80B)
static constexpr int ASZ = BM * LDT;
static constexpr int BSZ = BN * LDT;
static constexpr int STAGE = ASZ + BSZ;
static constexpr int GEMM_SMEM = 2 * STAGE * 2;  // ~40KB

template <bool A_HALF, bool SCALE_EPI>
__global__ __launch_bounds__(256)
void mma_gemm_fp16(const void* __restrict__ Aptr,
                   const __half* __restrict__ BT,   // [N][K] fp16
                   __half* __restrict__ C16,
                   int M, int N, int K) {
    extern __shared__ __half smemh[];

    const int tid  = threadIdx.x;
    const int wid  = tid >> 5;
    const int lane = tid & 31;
    const int g    = lane >> 2;
    const int t    = lane & 3;
    const int wrow = (wid >> 2) * 64;
    const int wcol = (wid & 3) * 32;
    const int rowBase = blockIdx.y * BM;
    const int colBase = blockIdx.x * BN;

    const int a_r = lane & 15;
    const int a_c = (lane >> 4) * 8;
    const int b_n = ((lane >> 4) << 3) + (lane & 7);
    const int b_k = ((lane >> 3) & 1) * 8;

    float4 a_stf[4];
    uint4  a_sth[2];
    uint4  b_st[2];

    auto load_stage = [&](int k0) {
        if (A_HALF) {
            const __half* Ah = (const __half*)Aptr;
            #pragma unroll
            for (int it = 0; it < 2; it++) {
                const int idx = tid + it * 256;
                const int r  = idx >> 2;
                const int c8 = (idx & 3) * 8;
                const int gr = rowBase + r;
                a_sth[it] = (gr < M)
                    ? *reinterpret_cast<const uint4*>(Ah + (size_t)gr * K + k0 + c8)
                    : make_uint4(0u, 0u, 0u, 0u);
            }
        } else {
            const float* Af = (const float*)Aptr;
            #pragma unroll
            for (int it = 0; it < 4; it++) {
                const int idx = tid + it * 256;
                const int r  = idx >> 3;
                const int c4 = (idx & 7) * 4;
                const int gr = rowBase + r;
                a_stf[it] = (gr < M)
                    ? *reinterpret_cast<const float4*>(Af + (size_t)gr * K + k0 + c4)
                    : make_float4(0.f, 0.f, 0.f, 0.f);
            }
        }
        #pragma unroll
        for (int it = 0; it < 2; it++) {
            const int idx = tid + it * 256;
            const int n  = idx >> 2;
            const int c8 = (idx & 3) * 8;
            b_st[it] = *reinterpret_cast<const uint4*>(
                BT + (size_t)(colBase + n) * K + k0 + c8);
        }
    };

    auto store_stage = [&](__half* As, __half* Bs) {
        if (A_HALF) {
            #pragma unroll
            for (int it = 0; it < 2; it++) {
                const int idx = tid + it * 256;
                const int r  = idx >> 2;
                const int c8 = (idx & 3) * 8;
                *reinterpret_cast<uint4*>(As + r * LDT + c8) = a_sth[it];
            }
        } else {
            #pragma unroll
            for (int it = 0; it < 4; it++) {
                const int idx = tid + it * 256;
                const int r  = idx >> 3;
                const int c4 = (idx & 7) * 4;
                const __half2 h01 = __floats2half2_rn(a_stf[it].x, a_stf[it].y);
                const __half2 h23 = __floats2half2_rn(a_stf[it].z, a_stf[it].w);
                uint2 u;
                u.x = *reinterpret_cast<const uint32_t*>(&h01);
                u.y = *reinterpret_cast<const uint32_t*>(&h23);
                *reinterpret_cast<uint2*>(As + r * LDT + c4) = u;
            }
        }
        #pragma unroll
        for (int it = 0; it < 2; it++) {
            const int idx = tid + it * 256;
            const int n  = idx >> 2;
            const int c8 = (idx & 3) * 8;
            *reinterpret_cast<uint4*>(Bs + n * LDT + c8) = b_st[it];
        }
    };

    float acc[4][4][4];
    #pragma unroll
    for (int i = 0; i < 4; i++)
        #pragma unroll
        for (int j = 0; j < 4; j++)
            #pragma unroll
            for (int c = 0; c < 4; c++) acc[i][j][c] = 0.0f;

    load_stage(0);

    const int ntiles = K / BK;
    for (int it = 0; it < ntiles; it++) {
        __half* As = smemh + (it & 1) * STAGE;
        __half* Bs = As + ASZ;

        store_stage(As, Bs);
        __syncthreads();
        if (it + 1 < ntiles) load_stage((it + 1) * BK);

        #pragma unroll
        for (int ks = 0; ks < 2; ks++) {
            const int kk = ks * 16;
            uint32_t af[4][4], bf[4][2];
            #pragma unroll
            for (int i = 0; i < 4; i++) {
                const uint32_t addr = (uint32_t)__cvta_generic_to_shared(
                    &As[(wrow + i * 16 + a_r) * LDT + kk + a_c]);
                LDSM_X4(af[i][0], af[i][1], af[i][2], af[i][3], addr);
            }
            #pragma unroll
            for (int p = 0; p < 2; p++) {
                const uint32_t addr = (uint32_t)__cvta_generic_to_shared(
                    &Bs[(wcol + p * 16 + b_n) * LDT + kk + b_k]);
                LDSM_X4(bf[2 * p][0], bf[2 * p][1], bf[2 * p + 1][0], bf[2 * p + 1][1], addr);
            }
            #pragma unroll
            for (int i = 0; i < 4; i++)
                #pragma unroll
                for (int j = 0; j < 4; j++)
                    mma_16x8x16(acc[i][j], af[i], bf[j]);
        }
    }

    #pragma unroll
    for (int i = 0; i < 4; i++) {
        #pragma unroll
        for (int half = 0; half < 2; half++) {
            const int gr = rowBase + wrow + i * 16 + g + half * 8;
            if (gr < M) {
                const float d = SCALE_EPI ? g_dinv[gr] : 1.0f;
                __half* dst = C16 + (size_t)gr * N + colBase + wcol;
                #pragma unroll
                for (int j = 0; j < 4; j++) {
                    const __half2 hv = __floats2half2_rn(acc[i][j][half * 2] * d,
                                                         acc[i][j][half * 2 + 1] * d);
                    *reinterpret_cast<__half2*>(dst + j * 8 + 2 * t) = hv;
                }
            }
        }
    }
}

// -------- weight transpose+convert: W[K][N] fp32 -> WT[N][K] fp16 -----------
__global__ void transpose_w_kernel(const float* __restrict__ W,
                                   __half* __restrict__ WT,
                                   int K, int N) {
    __shared__ float tile[32][33];
    const int k0 = blockIdx.y * 32;
    const int n0 = blockIdx.x * 32;
    const int tx = threadIdx.x, ty = threadIdx.y;   // 32 x 8
    #pragma unroll
    for (int i = 0; i < 32; i += 8)
        tile[ty + i][tx] = W[(size_t)(k0 + ty + i) * N + n0 + tx];
    __syncthreads();
    #pragma unroll
    for (int i = 0; i < 32; i += 8)
        WT[(size_t)(n0 + ty + i) * K + k0 + tx] = __float2half_rn(tile[tx][ty + i]);
}

// ======================= graph-side kernels =================================
__device__ __forceinline__ long long edge_get(const void* p, long long i) {
    return g_is64 ? ((const long long*)p)[i] : (long long)((const int*)p)[i];
}

__global__ void prep_kernel(const unsigned int* __restrict__ w, int nwords, int n) {
    if ((int)blockIdx.x == (int)gridDim.x - 1) {
        __shared__ unsigned int s_or;
        if (threadIdx.x == 0) {
            s_or = 0u;
            g_scan_count = 0;
            g_scan_ready = 0;
        }
        __syncthreads();
        unsigned int v = 0u;
        for (int i = 2 * threadIdx.x + 1; i < nwords; i += 2 * blockDim.x) v |= w[i];
        atomicOr(&s_or, v);
        __syncthreads();
        if (threadIdx.x == 0) g_is64 = (s_or == 0u) ? 1 : 0;
        return;
    }
    const int i = blockIdx.x * blockDim.x + threadIdx.x;
    if (i < n) g_indeg[i] = 0;
}

// 4 edges per thread: 4 independent loads (MLP), 4 atomics.
__global__ void indeg_kernel(const void* __restrict__ edges, int E) {
    const int base = 4 * (blockIdx.x * blockDim.x + threadIdx.x);
    if (base >= E) return;
    const int n = min(4, E - base);
    int r[4];
    #pragma unroll
    for (int k = 0; k < 4; k++)
        if (k < n) r[k] = (int)edge_get(edges, base + k);
    #pragma unroll
    for (int k = 0; k < 4; k++)
        if (k < n) atomicAdd(&g_indeg[r[k]], 1);
}

__global__ void scan_fused_kernel(int n, int nb) {
    __shared__ int s[256];
    __shared__ int s_prev;
    __shared__ int s_islast;
    const int t = threadIdx.x;
    const int bid = blockIdx.x;
    const int i = bid * 256 + t;

    int v = 0;
    if (i < n) {
        v = g_indeg[i];
        g_dinv[i] = rsqrtf((float)(v + 1));
    }
    s[t] = v;
    __syncthreads();
    #pragma unroll
    for (int off = 1; off < 256; off <<= 1) {
        int x = (t >= off) ? s[t - off] : 0;
        __syncthreads();
        s[t] += x;
        __syncthreads();
    }
    const int incl  = s[t];
    const int total = s[255];

    if (t == 0) {
        g_bsum[bid] = total;
        __threadfence();
        const int done = atomicAdd(&g_scan_count, 1);
        s_islast = (done == nb - 1) ? 1 : 0;
    }
    __syncthreads();

    if (s_islast) {
        int bv = (t < nb) ? g_bsum[t] : 0;
        s[t] = bv;
        __syncthreads();
        #pragma unroll
        for (int off = 1; off < 256; off <<= 1) {
            int x = (t >= off) ? s[t - off] : 0;
            __syncthreads();
            s[t] += x;
            __syncthreads();
        }
        if (t < nb) g_bpre[t] = s[t] - bv;
        __threadfence();
        __syncthreads();
        if (t == 0) atomicExch(&g_scan_ready, 1);
    }

    if (t == 0) {
        while (atomicAdd(&g_scan_ready, 0) == 0) {}
        __threadfence();
        s_prev = g_bpre[bid];
    }
    __syncthreads();

    if (i < n) {
        const int fin = incl + s_prev;
        g_off[i + 1] = fin;
        if (i + 1 < n) g_cursor[i + 1] = fin;
        if (i == 0) { g_off[0] = 0; g_cursor[0] = 0; }
    }
}

// 4 edges per thread: batched dst+src loads, then slot atomics + stores.
__global__ void fill_kernel(const void* __restrict__ edges, int E) {
    const int base = 4 * (blockIdx.x * blockDim.x + threadIdx.x);
    if (base >= E) return;
    const int n = min(4, E - base);
    int r[4], c[4];
    #pragma unroll
    for (int k = 0; k < 4; k++)
        if (k < n) r[k] = (int)edge_get(edges, base + k);
    #pragma unroll
    for (int k = 0; k < 4; k++)
        if (k < n) c[k] = (int)edge_get(edges, (long long)E + base + k);
    #pragma unroll
    for (int k = 0; k < 4; k++)
        if (k < n) {
            const int slot = atomicAdd(&g_cursor[r[k]], 1);
            g_elist[slot] = c[k];
        }
}

// ---- gather aggregation: SPLIT warps per destination node ------------------
template <int F, int SPLIT, bool RELU, bool SCALE_NBR, bool OUT_HALF>
__global__ void gather_kernel(const __half* __restrict__ hf,
                              const float* __restrict__ bias,
                              void* __restrict__ outp,
                              int M) {
    const int wunit = (int)((blockIdx.x * blockDim.x + threadIdx.x) >> 5);
    const int lane = threadIdx.x & 31;
    const int node = wunit / SPLIT;
    const int part = wunit - node * SPLIT;
    if (node >= M) return;
    const int fofs = part * (F / SPLIT) + lane * 4;

    const float d = g_dinv[node];
    const float selfs = SCALE_NBR ? d : 1.0f;

    float acc[4];
    {
        const uint2 raw = __ldg(reinterpret_cast<const uint2*>(hf + (size_t)node * F + fofs));
        const __half2* hp = reinterpret_cast<const __half2*>(&raw);
        const float2 f0 = __half22float2(hp[0]);
        const float2 f1 = __half22float2(hp[1]);
        acc[0] = selfs * f0.x; acc[1] = selfs * f0.y;
        acc[2] = selfs * f1.x; acc[3] = selfs * f1.y;
    }

    const int beg = g_off[node];
    const int end = g_off[node + 1];
    for (int i = beg; i < end; i += 32) {
        const int   my  = (i + lane < end) ? g_elist[i + lane] : 0;
        const float myd = SCALE_NBR ? g_dinv[my] : 1.0f;
        const int cnt = min(32, end - i);
        #pragma unroll 4
        for (int j = 0; j < cnt; j++) {
            const int   c  = __shfl_sync(0xffffffffu, my,  j);
            const float dc = SCALE_NBR ? __shfl_sync(0xffffffffu, myd, j) : 1.0f;
            const uint2 raw = __ldg(reinterpret_cast<const uint2*>(hf + (size_t)c * F + fofs));
            const __half2* hp = reinterpret_cast<const __half2*>(&raw);
            const float2 f0 = __half22float2(hp[0]);
            const float2 f1 = __half22float2(hp[1]);
            if (SCALE_NBR) {
                acc[0] = fmaf(dc, f0.x, acc[0]); acc[1] = fmaf(dc, f0.y, acc[1]);
                acc[2] = fmaf(dc, f1.x, acc[2]); acc[3] = fmaf(dc, f1.y, acc[3]);
            } else {
                acc[0] += f0.x; acc[1] += f0.y;
                acc[2] += f1.x; acc[3] += f1.y;
            }
        }
    }

    const float4 bv = __ldg(reinterpret_cast<const float4*>(bias + fofs));
    float4 v;
    v.x = fmaf(d, acc[0], bv.x);
    v.y = fmaf(d, acc[1], bv.y);
    v.z = fmaf(d, acc[2], bv.z);
    v.w = fmaf(d, acc[3], bv.w);
    if (RELU) {
        v.x = fmaxf(v.x, 0.f); v.y = fmaxf(v.y, 0.f);
        v.z = fmaxf(v.z, 0.f); v.w = fmaxf(v.w, 0.f);
    }
    if (OUT_HALF) {
        const __half2 h01 = __floats2half2_rn(v.x, v.y);
        const __half2 h23 = __floats2half2_rn(v.z, v.w);
        uint2 u;
        u.x = *reinterpret_cast<const uint32_t*>(&h01);
        u.y = *reinterpret_cast<const uint32_t*>(&h23);
        *reinterpret_cast<uint2*>((__half*)outp + (size_t)node * F + fofs) = u;
    } else {
        *reinterpret_cast<float4*>((float*)outp + (size_t)node * F + fofs) = v;
    }
}

// -------- static side stream for CSR/GEMM1 overlap (created pre-capture) ----
static cudaStream_t g_s2 = nullptr;
static cudaEvent_t  g_evFork = nullptr, g_evJoin = nullptr;
static bool g_streams_ok = false;
namespace {
struct StreamInit {
    StreamInit() {
        g_streams_ok =
            cudaStreamCreateWithFlags(&g_s2, cudaStreamNonBlocking) == cudaSuccess &&
            cudaEventCreateWithFlags(&g_evFork, cudaEventDisableTiming) == cudaSuccess &&
            cudaEventCreateWithFlags(&g_evJoin, cudaEventDisableTiming) == cudaSuccess;
    }
} g_stream_init;
}

// ---------------------------------------------------------------
extern "C" void kernel_launch(void* const* d_in, const int* in_sizes, int n_in,
                              void* d_out, int out_size) {
    const float* x     = (const float*)d_in[0];
    const void*  edges = d_in[1];
    const float* W1    = (const float*)d_in[2];
    const float* b1    = (const float*)d_in[3];
    const float* W2    = (const float*)d_in[4];
    const float* b2    = (const float*)d_in[5];
    float* out = (float*)d_out;

    const int M = in_sizes[0] / F_IN;
    const int E = in_sizes[1] / 2;
    const int NB = (M + 255) / 256;

    __half* h1f  = nullptr;  cudaGetSymbolAddress((void**)&h1f,  g_h1f);
    __half* agg1 = nullptr;  cudaGetSymbolAddress((void**)&agg1, g_agg1);
    __half* h2f  = nullptr;  cudaGetSymbolAddress((void**)&h2f,  g_h2f);
    __half* w1t  = nullptr;  cudaGetSymbolAddress((void**)&w1t,  g_w1t);
    __half* w2t  = nullptr;  cudaGetSymbolAddress((void**)&w2t,  g_w2t);

    const dim3 grid1(F_HID / BN, (M + BM - 1) / BM);
    const dim3 grid2(F_OUT / BN, (M + BM - 1) / BM);
    const dim3 tblk(32, 8);
    const int eb4 = ((E + 3) / 4 + 255) / 256;   // 4 edges per thread
    int nwords = 2 * E;
    if (nwords > 4096) nwords = 4096;

    if (g_streams_ok) {
        // side: prep (detect+zero+flags) -> indeg -> fused scan -> fill -> w2t
        cudaEventRecord(g_evFork, 0);
        cudaStreamWaitEvent(g_s2, g_evFork, 0);

        prep_kernel<<<NB + 1, 256, 0, g_s2>>>((const unsigned int*)edges, nwords, M);
        indeg_kernel<<<eb4, 256, 0, g_s2>>>(edges, E);
        scan_fused_kernel<<<NB, 256, 0, g_s2>>>(M, NB);
        fill_kernel<<<eb4, 256, 0, g_s2>>>(edges, E);
        transpose_w_kernel<<<dim3(F_OUT / 32, F_HID / 32), tblk, 0, g_s2>>>(W2, w2t, F_HID, F_OUT);
        cudaEventRecord(g_evJoin, g_s2);

        // main: w1t transpose -> GEMM1 (no dependency on detect/CSR)
        transpose_w_kernel<<<dim3(F_HID / 32, F_IN / 32), tblk>>>(W1, w1t, F_IN, F_HID);
        mma_gemm_fp16<false, false><<<grid1, 256, GEMM_SMEM>>>(x, w1t, h1f, M, F_HID, F_IN);

        cudaStreamWaitEvent(0, g_evJoin, 0);
    } else {
        prep_kernel<<<NB + 1, 256>>>((const unsigned int*)edges, nwords, M);
        indeg_kernel<<<eb4, 256>>>(edges, E);
        scan_fused_kernel<<<NB, 256>>>(M, NB);
        fill_kernel<<<eb4, 256>>>(edges, E);
        transpose_w_kernel<<<dim3(F_HID / 32, F_IN / 32), tblk>>>(W1, w1t, F_IN, F_HID);
        transpose_w_kernel<<<dim3(F_OUT / 32, F_HID / 32), tblk>>>(W2, w2t, F_HID, F_OUT);
        mma_gemm_fp16<false, false><<<grid1, 256, GEMM_SMEM>>>(x, w1t, h1f, M, F_HID, F_IN);
    }

    // gather1 (2 warps/node): agg1[r] = relu(dinv[r]*(dinv[r]*h1[r] + sum dinv[c]*h1[c]) + b1)
    {
        const long long warps = (long long)M * 2;
        gather_kernel<F_HID, 2, true, true, true>
            <<<(int)((warps * 32 + 255) / 256), 256>>>(h1f, b1, agg1, M);
    }

    // GEMM2: hs2 = (agg1 @ W2) * dinv[row]  (A fp16 direct)
    mma_gemm_fp16<true, true><<<grid2, 256, GEMM_SMEM>>>(agg1, w2t, h2f, M, F_OUT, F_HID);

    // gather2 (1 warp/node): out[r] = dinv[r]*(hs2[r] + sum hs2[c]) + b2
    {
        const long long warps = (long long)M;
        gather_kernel<F_OUT, 1, false, false, false>
            <<<(int)((warps * 32 + 255) / 256), 256>>>(h2f, b2, out, M);
    }
}